// round 1
// baseline (speedup 1.0000x reference)
#include <cuda_runtime.h>
#include <float.h>

// ROI adaptive max pool 7x7.
// images: [N=8, C=256, H=56, W=56] f32
// rois:   [R=256, 4] f32 relative (x1,y1,x2,y2)
// roi_idx:[R=256] i32
// out:    [R, C, 7, 7] f32
//
// Strategy: separable pooling. One block per (roi, 4-channel group).
// Phase 1: threadIdx.x = image column; each active column computes the 7
//          row-bin maxes for its column (coalesced loads along W) -> shared.
// Phase 2: 196 threads each reduce one (channel, i, j) column-bin from shared.

#define Hc 56
#define Wc 56
#define Cc 256
#define Rc 256
#define OUTc 7
#define CPB 4  // channels per block

__global__ __launch_bounds__(256) void roipool_kernel(
    const float* __restrict__ images,
    const float* __restrict__ rois,
    const int* __restrict__ roi_idx,
    float* __restrict__ out)
{
    __shared__ float rowp[CPB][OUTc][Wc + 8];  // +8 pad vs bank conflicts

    const int r  = blockIdx.y;
    const int cg = blockIdx.x;
    const int tx = threadIdx.x;  // 0..63
    const int ty = threadIdx.y;  // 0..CPB-1

    // ROI bounds (cheap; every thread computes them)
    const float r0 = rois[r * 4 + 0];
    const float r1 = rois[r * 4 + 1];
    const float r2 = rois[r * 4 + 2];
    const float r3 = rois[r * 4 + 3];
    const int x1 = (int)floorf(r0 * (float)Wc);
    const int y1 = (int)floorf(r1 * (float)Hc);
    const int x2 = (int)ceilf (r2 * (float)Wc);
    const int y2 = (int)ceilf (r3 * (float)Hc);
    const int Hr = y2 - y1;
    const int Wr = x2 - x1;

    const int n = roi_idx[r];
    const int c = cg * CPB + ty;
    const float* __restrict__ img =
        images + (size_t)(n * Cc + c) * (Hc * Wc);

    // Phase 1: per-column row-bin maxes
    if (tx >= x1 && tx < x2) {
        #pragma unroll
        for (int i = 0; i < OUTc; i++) {
            const int s = y1 + (i * Hr) / OUTc;
            const int e = y1 + ((i + 1) * Hr + OUTc - 1) / OUTc;  // ceil
            float m = -FLT_MAX;
            for (int y = s; y < e; y++)
                m = fmaxf(m, img[y * Wc + tx]);
            rowp[ty][i][tx] = m;
        }
    }
    __syncthreads();

    // Phase 2: column-bin maxes over shared rowp
    const int tid = ty * 64 + tx;
    if (tid < CPB * OUTc * OUTc) {
        const int cc = tid / (OUTc * OUTc);
        const int ij = tid % (OUTc * OUTc);
        const int i = ij / OUTc;
        const int j = ij % OUTc;
        const int s = x1 + (j * Wr) / OUTc;
        const int e = x1 + ((j + 1) * Wr + OUTc - 1) / OUTc;  // ceil
        float m = -FLT_MAX;
        for (int x = s; x < e; x++)
            m = fmaxf(m, rowp[cc][i][x]);
        out[(((size_t)r * Cc + (cg * CPB + cc)) * OUTc + i) * OUTc + j] = m;
    }
}

extern "C" void kernel_launch(void* const* d_in, const int* in_sizes, int n_in,
                              void* d_out, int out_size) {
    const float* images = (const float*)d_in[0];
    const float* rois   = (const float*)d_in[1];
    const int*   roi_idx = (const int*)d_in[2];
    float* out = (float*)d_out;

    dim3 grid(Cc / CPB, Rc);   // (64, 256) = 16384 blocks
    dim3 block(64, CPB);       // 256 threads
    roipool_kernel<<<grid, block>>>(images, rois, roi_idx, out);
}

// round 2
// speedup vs baseline: 1.6199x; 1.6199x over previous
#include <cuda_runtime.h>
#include <float.h>

// ROI adaptive max pool 7x7 — separable, float4-vectorized.
// images: [8,256,56,56] f32; rois: [256,4] f32; roi_idx: [256] i32
// out: [256,256,7,7] f32
//
// Block = (roi, 16-channel group). blockDim = (16 quads, 16 channels).
// Phase 1: thread (q, c) loads float4 column-quads (LDG.128, coalesced,
//          always in-bounds since full rows exist) and computes the 7
//          row-bin maxes for its 4 columns -> shared rowp.
// Phase 2: thread per output element (c,i,j), j fastest -> coalesced STG.

#define Hc 56
#define Wc 56
#define Cc 256
#define Rc 256
#define OUTN 7
#define CPB 16

__global__ __launch_bounds__(256) void roipool_kernel(
    const float* __restrict__ images,
    const float* __restrict__ rois,
    const int* __restrict__ roi_idx,
    float* __restrict__ out)
{
    // stride 60 floats = 240B (16B-aligned for float4 stores, breaks 32-bank repeat)
    __shared__ float rowp[CPB][OUTN][60];

    const int r  = blockIdx.y;
    const int cg = blockIdx.x;
    const int tx = threadIdx.x;  // quad slot 0..15 (14 used)
    const int ty = threadIdx.y;  // channel-in-group 0..15

    const float4 rv = ((const float4*)rois)[r];  // broadcast load
    const int x1 = (int)floorf(rv.x * (float)Wc);
    const int y1 = (int)floorf(rv.y * (float)Hc);
    const int x2 = (int)ceilf (rv.z * (float)Wc);
    const int y2 = (int)ceilf (rv.w * (float)Hc);
    const int Hr = y2 - y1;
    const int Wr = x2 - x1;

    const int n = roi_idx[r];
    const int c = cg * CPB + ty;
    const float* __restrict__ img =
        images + (size_t)(n * Cc + c) * (Hc * Wc);

    // ---- Phase 1: row-bin maxes, 4 columns per thread via float4 ----
    const int qlo = x1 >> 2;
    const int qhi = (x2 + 3) >> 2;
    if (tx >= qlo && tx < qhi) {
        const float4* __restrict__ col4 = (const float4*)img + tx;  // +14 per row
        #pragma unroll
        for (int i = 0; i < OUTN; i++) {
            const int s = y1 + (i * Hr) / OUTN;
            const int e = y1 + ((i + 1) * Hr + OUTN - 1) / OUTN;  // ceil
            float4 m = make_float4(-FLT_MAX, -FLT_MAX, -FLT_MAX, -FLT_MAX);
            for (int y = s; y < e; y++) {
                const float4 v = col4[y * (Wc / 4)];
                m.x = fmaxf(m.x, v.x);
                m.y = fmaxf(m.y, v.y);
                m.z = fmaxf(m.z, v.z);
                m.w = fmaxf(m.w, v.w);
            }
            *(float4*)&rowp[ty][i][tx * 4] = m;
        }
    }
    __syncthreads();

    // ---- Phase 2: col-bin maxes from shared, one output per thread ----
    const int tid = ty * 16 + tx;
    float* __restrict__ outg = out + ((size_t)r * Cc + cg * CPB) * (OUTN * OUTN);
    #pragma unroll
    for (int o = tid; o < CPB * OUTN * OUTN; o += 256) {
        const int cc = o / (OUTN * OUTN);
        const int ij = o % (OUTN * OUTN);
        const int i = ij / OUTN;
        const int j = ij % OUTN;
        const int s = x1 + (j * Wr) / OUTN;
        const int e = x1 + ((j + 1) * Wr + OUTN - 1) / OUTN;  // ceil
        float m = -FLT_MAX;
        for (int x = s; x < e; x++)
            m = fmaxf(m, rowp[cc][i][x]);
        outg[o] = m;  // o == cc*49 + i*7 + j -> contiguous, coalesced
    }
}

extern "C" void kernel_launch(void* const* d_in, const int* in_sizes, int n_in,
                              void* d_out, int out_size) {
    const float* images  = (const float*)d_in[0];
    const float* rois    = (const float*)d_in[1];
    const int*   roi_idx = (const int*)d_in[2];
    float* out = (float*)d_out;

    dim3 grid(Cc / CPB, Rc);   // (16, 256) = 4096 blocks
    dim3 block(16, CPB);       // 256 threads
    roipool_kernel<<<grid, block>>>(images, rois, roi_idx, out);
}